// round 14
// baseline (speedup 1.0000x reference)
#include <cuda_runtime.h>
#include <math.h>

// ---------------------------------------------------------------------------
// Problem constants
// ---------------------------------------------------------------------------
#define BB    16
#define CCH   768
#define NN_   1024           // 32*32 tokens
#define HIDD  3072
#define NROW  112            // 56 complex modes -> 112 real rows
#define XFB   (NROW*CCH)     // 86016 floats per batch of xf

// ---------------------------------------------------------------------------
// Scratch buffers (static device globals; no allocation anywhere)
// ---------------------------------------------------------------------------
__device__ float g_t  [(long long)BB*NN_*CCH];      // residual stream [B,N,C]
__device__ float g_f  [(long long)BB*NN_*CCH];      // multi-purpose   [B,N,C]
__device__ float g_qkv[(long long)BB*NN_*3*CCH];    // qkv             [B,N,3C]
__device__ float g_u  [(long long)BB*NN_*HIDD];     // mlp hidden
__device__ float g_u2 [(long long)BB*NN_*HIDD];     // dwconv out
__device__ float g_kv [(long long)BB*8*96*96];      // per-head kv
__device__ float g_xf [(long long)BB*XFB];          // fwd DFT coeffs
__device__ float g_xf2[(long long)BB*XFB];          // mixed coeffs
__device__ float g_dftF[NROW*NN_];                  // forward DFT basis
__device__ float g_dftI[NN_*NROW];                  // inverse DFT basis

// ---------------------------------------------------------------------------
// DFT basis. Global mode m: set=m/28 (set0: ky=0..6, set1: ky=25..31),
// mm=m%28, ky_local=mm/4, kx=mm%4, theta = 2*pi*((ky*h + kx*w) mod 32)/32.
// Forward rows: 2m = sum cos * x, 2m+1 = -sum sin * x  (e^{-i theta}).
// Inverse: x[n] = sum_m (wgt/1024) * (Or*cos - Oi*sin), wgt = (kx==0)?1:2
// (reproduces irfft2 = irfft(ifft(axis=-2), axis=-1) incl. kx=0 imag discard).
// ---------------------------------------------------------------------------
__global__ void init_basis_kernel()
{
    int m = blockIdx.x;          // 0..55
    int n = threadIdx.x;         // 0..1023
    int set = m / 28, mm = m % 28;
    int ky = (set == 0) ? (mm >> 2) : (25 + (mm >> 2));
    int kx = mm & 3;
    int hh = n >> 5, ww = n & 31;
    int ph = (ky * hh + kx * ww) & 31;
    float theta = 6.283185307179586f * (float)ph / 32.0f;
    float c, s;
    sincosf(theta, &s, &c);
    g_dftF[(2*m)     * NN_ + n] =  c;
    g_dftF[(2*m + 1) * NN_ + n] = -s;
    float wgt = (kx == 0) ? 1.0f : 2.0f;
    g_dftI[n * NROW + 2*m]     =  wgt * c * (1.0f / 1024.0f);
    g_dftI[n * NROW + 2*m + 1] = -wgt * s * (1.0f / 1024.0f);
}

// ---------------------------------------------------------------------------
// Batched transpose: in [B, R, S] -> out [B, S, R].  R,S divisible by 32.
// ---------------------------------------------------------------------------
__global__ void transpose_kernel(const float* __restrict__ in,
                                 float* __restrict__ out, int R, int S)
{
    __shared__ float tile[32][33];
    int b = blockIdx.z;
    int s0 = blockIdx.x * 32, r0 = blockIdx.y * 32;
    const float* ib = in + (long long)b * R * S;
    float* ob = out + (long long)b * R * S;
    tile[threadIdx.y][threadIdx.x] =
        ib[(long long)(r0 + threadIdx.y) * S + s0 + threadIdx.x];
    __syncthreads();
    ob[(long long)(s0 + threadIdx.y) * R + r0 + threadIdx.x] =
        tile[threadIdx.x][threadIdx.y];
}

// ---------------------------------------------------------------------------
// Row LayerNorm over width Cw (divisible by 4).
//   mode 0: out = LN(in)
//   mode 1: out = gelu(LN(in))            (exact gelu)
//   mode 2: out = resid + LN(in)
// One block per row, 256 threads.
// ---------------------------------------------------------------------------
__global__ __launch_bounds__(256)
void ln_row_kernel(const float* __restrict__ in, const float* __restrict__ gam,
                   const float* __restrict__ bet, float* __restrict__ out,
                   const float* __restrict__ resid, int Cw, int mode)
{
    long long row = blockIdx.x;
    const float4* p = (const float4*)(in + row * Cw);
    int n4 = Cw >> 2;
    float s = 0.f, s2 = 0.f;
    for (int i = threadIdx.x; i < n4; i += 256) {
        float4 v = p[i];
        s  += v.x + v.y + v.z + v.w;
        s2 += v.x*v.x + v.y*v.y + v.z*v.z + v.w*v.w;
    }
    __shared__ float sh[16];
    for (int o = 16; o; o >>= 1) {
        s  += __shfl_xor_sync(0xffffffffu, s,  o);
        s2 += __shfl_xor_sync(0xffffffffu, s2, o);
    }
    int wid = threadIdx.x >> 5, lid = threadIdx.x & 31;
    if (lid == 0) { sh[wid] = s; sh[wid + 8] = s2; }
    __syncthreads();
    if (threadIdx.x < 32) {
        s  = (threadIdx.x < 8) ? sh[threadIdx.x]     : 0.f;
        s2 = (threadIdx.x < 8) ? sh[threadIdx.x + 8] : 0.f;
        for (int o = 4; o; o >>= 1) {
            s  += __shfl_xor_sync(0xffffffffu, s,  o);
            s2 += __shfl_xor_sync(0xffffffffu, s2, o);
        }
        if (threadIdx.x == 0) { sh[0] = s; sh[1] = s2; }
    }
    __syncthreads();
    float mean = sh[0] / (float)Cw;
    float rstd = rsqrtf(sh[1] / (float)Cw - mean * mean + 1e-5f);
    float4* q = (float4*)(out + row * Cw);
    const float4* gp = (const float4*)gam;
    const float4* bp = (const float4*)bet;
    const float4* rp = resid ? (const float4*)(resid + row * Cw) : (const float4*)0;
    for (int i = threadIdx.x; i < n4; i += 256) {
        float4 v = p[i], gv = gp[i], bv = bp[i];
        float o0 = (v.x - mean) * rstd * gv.x + bv.x;
        float o1 = (v.y - mean) * rstd * gv.y + bv.y;
        float o2 = (v.z - mean) * rstd * gv.z + bv.z;
        float o3 = (v.w - mean) * rstd * gv.w + bv.w;
        if (mode == 1) {
            o0 = 0.5f * o0 * (1.0f + erff(o0 * 0.70710678118654752f));
            o1 = 0.5f * o1 * (1.0f + erff(o1 * 0.70710678118654752f));
            o2 = 0.5f * o2 * (1.0f + erff(o2 * 0.70710678118654752f));
            o3 = 0.5f * o3 * (1.0f + erff(o3 * 0.70710678118654752f));
        } else if (mode == 2) {
            float4 rv = rp[i];
            o0 += rv.x; o1 += rv.y; o2 += rv.z; o3 += rv.w;
        }
        float4 ov; ov.x = o0; ov.y = o1; ov.z = o2; ov.w = o3;
        q[i] = ov;
    }
}

// ---------------------------------------------------------------------------
// Generic guarded tiled GEMM  C[M,N] = A[M,K] @ B[K,N]  (row-major, strided,
// batched over blockIdx.z).  BM=BN=64, BK=16, 256 threads, 4x4 per thread.
// ---------------------------------------------------------------------------
__global__ __launch_bounds__(256)
void gemm_generic(const float* __restrict__ A, const float* __restrict__ B,
                  float* __restrict__ C, int M, int N, int K,
                  int lda, int ldb, int ldc,
                  long long sA, long long sB, long long sC)
{
    A += sA * blockIdx.z; B += sB * blockIdx.z; C += sC * blockIdx.z;
    __shared__ float As[16][65];
    __shared__ float Bs[16][64];
    int tid = threadIdx.x;
    int brow = blockIdx.y * 64, bcol = blockIdx.x * 64;
    float acc[4][4] = {};
    int trow = (tid >> 4) << 2, tcol = (tid & 15) << 2;
    for (int k0 = 0; k0 < K; k0 += 16) {
        {
            int m  = tid >> 2;
            int kk = (tid & 3) << 2;
            int gr = brow + m;
            #pragma unroll
            for (int t = 0; t < 4; t++) {
                int gk = k0 + kk + t;
                As[kk + t][m] = (gr < M && gk < K) ? A[(long long)gr * lda + gk] : 0.f;
            }
        }
        {
            int kk = tid >> 4;
            int ci = (tid & 15) << 2;
            int gk = k0 + kk;
            #pragma unroll
            for (int t = 0; t < 4; t++) {
                int gc = bcol + ci + t;
                Bs[kk][ci + t] = (gk < K && gc < N) ? B[(long long)gk * ldb + gc] : 0.f;
            }
        }
        __syncthreads();
        #pragma unroll
        for (int kk = 0; kk < 16; kk++) {
            float a[4], bb[4];
            #pragma unroll
            for (int i = 0; i < 4; i++) a[i]  = As[kk][trow + i];
            #pragma unroll
            for (int j = 0; j < 4; j++) bb[j] = Bs[kk][tcol + j];
            #pragma unroll
            for (int i = 0; i < 4; i++)
                #pragma unroll
                for (int j = 0; j < 4; j++) acc[i][j] = fmaf(a[i], bb[j], acc[i][j]);
        }
        __syncthreads();
    }
    #pragma unroll
    for (int i = 0; i < 4; i++) {
        int gr = brow + trow + i;
        if (gr >= M) continue;
        #pragma unroll
        for (int j = 0; j < 4; j++) {
            int gc = bcol + tcol + j;
            if (gc < N) C[(long long)gr * ldc + gc] = acc[i][j];
        }
    }
}

// ---------------------------------------------------------------------------
// Big SGEMM: C[M,N] = A[M,K] @ B[K,N], all dims divisible (M%128==0, N%128==0,
// K%8==0).  BM=BN=128, BK=8, 256 threads, 8x8 per thread (split 4+4 halves).
// EPI bit0: += bias[N];  EPI bit1: C += (accumulate into existing C).
// ---------------------------------------------------------------------------
template <int EPI>
__global__ __launch_bounds__(256)
void sgemm128(const float* __restrict__ A, const float* __restrict__ B,
              float* __restrict__ C, const float* __restrict__ bias,
              int M, int N, int K)
{
    __shared__ float As[8][132];
    __shared__ float Bs[8][132];
    int tid = threadIdx.x;
    int brow = blockIdx.y * 128, bcol = blockIdx.x * 128;
    const float* Ab = A + (long long)brow * K;
    const float* Bb = B + bcol;

    int a_row  = tid >> 1;
    int a_col4 = (tid & 1) << 2;
    int b_row  = tid >> 5;
    int b_col4 = (tid & 31) << 2;
    int ty4 = (tid >> 4) << 2;
    int tx4 = (tid & 15) << 2;

    float acc[8][8] = {};
    for (int k0 = 0; k0 < K; k0 += 8) {
        float4 av = *(const float4*)(Ab + (long long)a_row * K + k0 + a_col4);
        As[a_col4 + 0][a_row] = av.x;
        As[a_col4 + 1][a_row] = av.y;
        As[a_col4 + 2][a_row] = av.z;
        As[a_col4 + 3][a_row] = av.w;
        float4 bv = *(const float4*)(Bb + (long long)(k0 + b_row) * N + b_col4);
        *(float4*)(&Bs[b_row][b_col4]) = bv;
        __syncthreads();
        #pragma unroll
        for (int kk = 0; kk < 8; kk++) {
            float a[8], bb[8];
            #pragma unroll
            for (int u = 0; u < 4; u++) {
                a[u]      = As[kk][ty4 + u];
                a[u + 4]  = As[kk][64 + ty4 + u];
                bb[u]     = Bs[kk][tx4 + u];
                bb[u + 4] = Bs[kk][64 + tx4 + u];
            }
            #pragma unroll
            for (int i = 0; i < 8; i++)
                #pragma unroll
                for (int j = 0; j < 8; j++)
                    acc[i][j] = fmaf(a[i], bb[j], acc[i][j]);
        }
        __syncthreads();
    }

    float bj[8];
    if (EPI & 1) {
        #pragma unroll
        for (int u = 0; u < 4; u++) {
            bj[u]     = bias[bcol + tx4 + u];
            bj[u + 4] = bias[bcol + 64 + tx4 + u];
        }
    }
    #pragma unroll
    for (int ih = 0; ih < 2; ih++) {
        #pragma unroll
        for (int u = 0; u < 4; u++) {
            int r = brow + ih * 64 + ty4 + u;
            float* crow = C + (long long)r * N + bcol;
            #pragma unroll
            for (int jh = 0; jh < 2; jh++) {
                float4 v;
                v.x = acc[ih*4 + u][jh*4 + 0];
                v.y = acc[ih*4 + u][jh*4 + 1];
                v.z = acc[ih*4 + u][jh*4 + 2];
                v.w = acc[ih*4 + u][jh*4 + 3];
                if (EPI & 1) {
                    v.x += bj[jh*4 + 0]; v.y += bj[jh*4 + 1];
                    v.z += bj[jh*4 + 2]; v.w += bj[jh*4 + 3];
                }
                float* p = crow + jh * 64 + tx4;
                if (EPI & 2) {
                    float4 o = *(float4*)p;
                    v.x += o.x; v.y += o.y; v.z += o.z; v.w += o.w;
                }
                *(float4*)p = v;
            }
        }
    }
}

// ---------------------------------------------------------------------------
// Spectral mode mixing (complex channel mix per retained mode).
// Grid: (96 o-tiles of 8, 2 sets).  Block: 224 threads = 8 o x 28 m.
// Weight layout w[i][o][ky][kx] -> flat (i*768+o)*28 + m : warp reads 32
// consecutive floats (fully coalesced).  16 batches in registers.
// ---------------------------------------------------------------------------
__global__ __launch_bounds__(224)
void mix_kernel(const float* __restrict__ w1r, const float* __restrict__ w1i,
                const float* __restrict__ w2r, const float* __restrict__ w2i)
{
    int set   = blockIdx.y;
    int otile = blockIdx.x;
    const float* Wr = set ? w2r : w1r;
    const float* Wi = set ? w2i : w1i;
    int tid = threadIdx.x;
    int o_loc = tid / 28;
    int m     = tid % 28;
    int o = otile * 8 + o_loc;
    int rowbase = 2 * (set * 28 + m);

    __shared__ float Xs[8 * 929];   // [ii][ (b*2+p)*29 + m ]
    float accR[16], accI[16];
    #pragma unroll
    for (int b = 0; b < 16; b++) { accR[b] = 0.f; accI[b] = 0.f; }

    for (int i0 = 0; i0 < 768; i0 += 8) {
        // cooperative load: 896 rows (m,b,p) x 8 i -> float4 per thread x8
        #pragma unroll
        for (int pass = 0; pass < 8; pass++) {
            int r  = pass * 112 + (tid >> 1);
            int i4 = (tid & 1) << 2;
            int m2  = r >> 5;
            int rem = r & 31;
            int b2  = rem >> 1;
            int p   = rem & 1;
            float4 v = *(const float4*)&g_xf[(long long)b2 * XFB +
                          (long long)(2 * (set * 28 + m2) + p) * 768 + i0 + i4];
            int off = (b2 * 2 + p) * 29 + m2;
            Xs[(i4 + 0) * 929 + off] = v.x;
            Xs[(i4 + 1) * 929 + off] = v.y;
            Xs[(i4 + 2) * 929 + off] = v.z;
            Xs[(i4 + 3) * 929 + off] = v.w;
        }
        __syncthreads();
        #pragma unroll
        for (int ii = 0; ii < 8; ii++) {
            long long i = i0 + ii;
            float wr = Wr[(i * 768 + o) * 28 + m];
            float wi = Wi[(i * 768 + o) * 28 + m];
            const float* xp = &Xs[ii * 929];
            #pragma unroll
            for (int b = 0; b < 16; b++) {
                float xr = xp[b * 58 + m];
                float xi = xp[b * 58 + 29 + m];
                accR[b] = fmaf(xr, wr, fmaf(-xi, wi, accR[b]));
                accI[b] = fmaf(xr, wi, fmaf( xi, wr, accI[b]));
            }
        }
        __syncthreads();
    }
    #pragma unroll
    for (int b = 0; b < 16; b++) {
        long long base = (long long)b * XFB + (long long)rowbase * 768 + o;
        g_xf2[base]       = accR[b];
        g_xf2[base + 768] = accI[b];
    }
}

// ---------------------------------------------------------------------------
// kv = softmax_n(K)^T @ V per (b,h).  One block per (b,h), 256 threads.
// Stats (online softmax over 1024 tokens) then tiled 96x96 GEMM.
// ---------------------------------------------------------------------------
__global__ __launch_bounds__(256)
void kv_kernel(const float* __restrict__ qkv, float* __restrict__ kvout)
{
    int bh = blockIdx.x; int b = bh >> 3, h = bh & 7;
    const float* kbase = qkv + (long long)b * NN_ * 2304 + 768  + h * 96;
    const float* vbase = qkv + (long long)b * NN_ * 2304 + 1536 + h * 96;
    int tid = threadIdx.x;

    __shared__ float smax[96], srs[96];
    if (tid < 96) {
        float m = -1e30f, s = 0.f;
        for (int n = 0; n < NN_; n++) {
            float v = kbase[(long long)n * 2304 + tid];
            if (v > m) { s = s * __expf(m - v) + 1.f; m = v; }
            else         s += __expf(v - m);
        }
        smax[tid] = m; srs[tid] = 1.f / s;
    }
    __syncthreads();

    __shared__ float Ks[32][97], Vs[32][97];
    float acc[6][6] = {};
    int ty = tid >> 4, tx = tid & 15;
    for (int n0 = 0; n0 < NN_; n0 += 32) {
        for (int e = tid; e < 32 * 96; e += 256) {
            int nn = e / 96, cch = e % 96;
            float kl = kbase[(long long)(n0 + nn) * 2304 + cch];
            Ks[nn][cch] = __expf(kl - smax[cch]) * srs[cch];
            Vs[nn][cch] = vbase[(long long)(n0 + nn) * 2304 + cch];
        }
        __syncthreads();
        #pragma unroll 8
        for (int nn = 0; nn < 32; nn++) {
            float a[6], c2[6];
            #pragma unroll
            for (int i = 0; i < 6; i++) a[i]  = Ks[nn][ty * 6 + i];
            #pragma unroll
            for (int j = 0; j < 6; j++) c2[j] = Vs[nn][tx * 6 + j];
            #pragma unroll
            for (int i = 0; i < 6; i++)
                #pragma unroll
                for (int j = 0; j < 6; j++) acc[i][j] = fmaf(a[i], c2[j], acc[i][j]);
        }
        __syncthreads();
    }
    #pragma unroll
    for (int i = 0; i < 6; i++)
        #pragma unroll
        for (int j = 0; j < 6; j++)
            kvout[(long long)bh * 9216 + (ty * 6 + i) * 96 + tx * 6 + j] = acc[i][j];
}

// ---------------------------------------------------------------------------
// fa = Q @ KV, fused epilogue a_pre = scale*fa + q*sigmoid(cv)  (in place
// over the cv buffer f, layout [B,N,C]).  Grid (8 n-tiles, 128 bh).
// ---------------------------------------------------------------------------
__global__ __launch_bounds__(256)
void fa_kernel(const float* __restrict__ qkv, const float* __restrict__ kv,
               float* __restrict__ f)
{
    int bh = blockIdx.y; int b = bh >> 3, h = bh & 7;
    int n0 = blockIdx.x * 128;
    const float* qbase = qkv + (long long)b * NN_ * 2304 + h * 96;

    __shared__ float Qs[128][33];
    __shared__ float KVs[32][97];
    float acc[8][6] = {};
    int tid = threadIdx.x, ty = tid >> 4, tx = tid & 15;

    for (int k0 = 0; k0 < 96; k0 += 32) {
        for (int e = tid; e < 128 * 32; e += 256) {
            int r = e >> 5, kk = e & 31;
            Qs[r][kk] = qbase[(long long)(n0 + r) * 2304 + k0 + kk];
        }
        for (int e = tid; e < 32 * 96; e += 256) {
            int kk = e / 96, c = e % 96;
            KVs[kk][c] = kv[(long long)bh * 9216 + (k0 + kk) * 96 + c];
        }
        __syncthreads();
        #pragma unroll 8
        for (int kk = 0; kk < 32; kk++) {
            float a[8], bv[6];
            #pragma unroll
            for (int i = 0; i < 8; i++) a[i]  = Qs[ty * 8 + i][kk];
            #pragma unroll
            for (int j = 0; j < 6; j++) bv[j] = KVs[kk][tx * 6 + j];
            #pragma unroll
            for (int i = 0; i < 8; i++)
                #pragma unroll
                for (int j = 0; j < 6; j++) acc[i][j] = fmaf(a[i], bv[j], acc[i][j]);
        }
        __syncthreads();
    }
    const float scale = 0.10206207261596575f;   // 96^-0.5
    #pragma unroll
    for (int i = 0; i < 8; i++) {
        int r = n0 + ty * 8 + i;
        #pragma unroll
        for (int j = 0; j < 6; j++) {
            int c = tx * 6 + j;
            long long idx = ((long long)b * NN_ + r) * 768 + h * 96 + c;
            float qv  = qbase[(long long)r * 2304 + c];
            float cvv = f[idx];
            f[idx] = scale * acc[i][j] + qv * (1.f / (1.f + __expf(-cvv)));
        }
    }
}

// ---------------------------------------------------------------------------
// Depthwise 3x3 SAME conv on [B, N(h,w), HID] layout + bias.
// Grid (HID/128, 1024, B), 128 threads over channels.
// ---------------------------------------------------------------------------
__global__ __launch_bounds__(128)
void dwconv_kernel(const float* __restrict__ u, const float* __restrict__ w,
                   const float* __restrict__ bias, float* __restrict__ out)
{
    int cchunk = blockIdx.x;
    int n = blockIdx.y;
    int b = blockIdx.z;
    int c = cchunk * 128 + threadIdx.x;

    __shared__ float ws[128 * 9];
    __shared__ float bs[128];
    for (int e = threadIdx.x; e < 128 * 9; e += 128)
        ws[e] = w[cchunk * 128 * 9 + e];
    bs[threadIdx.x] = bias[c];
    __syncthreads();

    int hh = n >> 5, ww = n & 31;
    float acc = bs[threadIdx.x];
    const float* base = u + (long long)b * NN_ * HIDD + c;
    #pragma unroll
    for (int dy = 0; dy < 3; dy++) {
        int h2 = hh + dy - 1;
        if (h2 < 0 || h2 > 31) continue;
        #pragma unroll
        for (int dx = 0; dx < 3; dx++) {
            int w2 = ww + dx - 1;
            if (w2 < 0 || w2 > 31) continue;
            acc = fmaf(base[(long long)(h2 * 32 + w2) * HIDD],
                       ws[threadIdx.x * 9 + dy * 3 + dx], acc);
        }
    }
    out[((long long)b * NN_ + n) * HIDD + c] = acc;
}

// ---------------------------------------------------------------------------
// Host driver
// ---------------------------------------------------------------------------
extern "C" void kernel_launch(void* const* d_in, const int* in_sizes, int n_in,
                              void* d_out, int out_size)
{
    const float* in[26];
    for (int i = 0; i < 26 && i < n_in; i++) in[i] = (const float*)d_in[i];

    const float *x, *ln1_g, *ln1_b, *w1r1, *w1i1, *w2r1, *w2i1, *wqkv;
    const float *w1r2, *w1i2, *w2r2, *w2i2, *wproj, *bproj, *ln2_g, *ln2_b;
    const float *fc1_w, *fc1_b, *ml1_g, *ml1_b, *dw_w, *dw_b, *fc2_w, *fc2_b;
    const float *ml2_g, *ml2_b;

    if (in_sizes[0] == 768) {               // alphabetical key order
        bproj = in[0];  dw_b  = in[1];  dw_w  = in[2];
        fc1_b = in[3];  fc1_w = in[4];  fc2_b = in[5];  fc2_w = in[6];
        w1i1  = in[7];  w1r1  = in[8];  w2i1  = in[9];  w2r1 = in[10];
        w1i2  = in[11]; w1r2  = in[12]; w2i2  = in[13]; w2r2 = in[14];
        ln1_b = in[15]; ln1_g = in[16]; ln2_b = in[17]; ln2_g = in[18];
        ml1_b = in[19]; ml1_g = in[20]; ml2_b = in[21]; ml2_g = in[22];
        wproj = in[23]; wqkv  = in[24]; x     = in[25];
    } else if (in_sizes[1] == 768) {        // reference() signature order
        x = in[0]; ln1_g = in[1]; ln1_b = in[2];
        w1r1 = in[3]; w1i1 = in[4]; w2r1 = in[5]; w2i1 = in[6];
        wqkv = in[7];
        w1r2 = in[8]; w1i2 = in[9]; w2r2 = in[10]; w2i2 = in[11];
        wproj = in[12]; bproj = in[13]; ln2_g = in[14]; ln2_b = in[15];
        fc1_w = in[16]; fc1_b = in[17]; ml1_g = in[18]; ml1_b = in[19];
        dw_w  = in[20]; dw_b  = in[21]; fc2_w = in[22]; fc2_b = in[23];
        ml2_g = in[24]; ml2_b = in[25];
    } else {                                // setup_inputs() insertion order
        x = in[0];
        w1r1 = in[1]; w1i1 = in[2]; w2r1 = in[3]; w2i1 = in[4];
        w1r2 = in[5]; w1i2 = in[6]; w2r2 = in[7]; w2i2 = in[8];
        wqkv = in[9]; wproj = in[10]; bproj = in[11];
        fc1_w = in[12]; fc1_b = in[13]; fc2_w = in[14]; fc2_b = in[15];
        dw_w  = in[16]; dw_b  = in[17];
        ln1_g = in[18]; ln1_b = in[19]; ln2_g = in[20]; ln2_b = in[21];
        ml1_g = in[22]; ml1_b = in[23]; ml2_g = in[24]; ml2_b = in[25];
    }

    float *t_, *f_, *qkv_, *u_, *u2_, *kv_, *xf_, *xf2_, *dftF_, *dftI_;
    cudaGetSymbolAddress((void**)&t_,   g_t);
    cudaGetSymbolAddress((void**)&f_,   g_f);
    cudaGetSymbolAddress((void**)&qkv_, g_qkv);
    cudaGetSymbolAddress((void**)&u_,   g_u);
    cudaGetSymbolAddress((void**)&u2_,  g_u2);
    cudaGetSymbolAddress((void**)&kv_,  g_kv);
    cudaGetSymbolAddress((void**)&xf_,  g_xf);
    cudaGetSymbolAddress((void**)&xf2_, g_xf2);
    cudaGetSymbolAddress((void**)&dftF_, g_dftF);
    cudaGetSymbolAddress((void**)&dftI_, g_dftI);

    float* outp = (float*)d_out;

    init_basis_kernel<<<56, 1024>>>();

    // x [B,C,N] -> f [B,N,C]; t = LN1(f)
    transpose_kernel<<<dim3(32, 24, BB), dim3(32, 32)>>>(x, f_, CCH, NN_);
    ln_row_kernel<<<BB * NN_, 256>>>(f_, ln1_g, ln1_b, t_, (const float*)0, CCH, 0);

    // ---- spectral conv 1 (on t) ----
    gemm_generic<<<dim3(12, 2, BB), 256>>>(dftF_, t_, xf_,
        NROW, CCH, NN_, NN_, CCH, CCH, 0, (long long)NN_ * CCH, XFB);
    mix_kernel<<<dim3(96, 2), 224>>>(w1r1, w1i1, w2r1, w2i1);
    gemm_generic<<<dim3(12, 16, BB), 256>>>(dftI_, xf2_, f_,
        NN_, CCH, NROW, NROW, CCH, CCH, 0, XFB, (long long)NN_ * CCH);

    // qkv = f @ wqkv
    sgemm128<0><<<dim3(18, 128), 256>>>(f_, wqkv, qkv_, (const float*)0,
                                        BB * NN_, 3 * CCH, CCH);

    // ---- spectral conv 2 (on v slice of qkv) ----
    gemm_generic<<<dim3(12, 2, BB), 256>>>(dftF_, qkv_ + 1536, xf_,
        NROW, CCH, NN_, NN_, 3 * CCH, CCH, 0, (long long)NN_ * 3 * CCH, XFB);
    mix_kernel<<<dim3(96, 2), 224>>>(w1r2, w1i2, w2r2, w2i2);
    gemm_generic<<<dim3(12, 16, BB), 256>>>(dftI_, xf2_, f_,
        NN_, CCH, NROW, NROW, CCH, CCH, 0, XFB, (long long)NN_ * CCH);   // f = cv

    // attention
    kv_kernel<<<BB * 8, 256>>>(qkv_, kv_);
    fa_kernel<<<dim3(8, BB * 8), 256>>>(qkv_, kv_, f_);                  // f = a_pre

    // t += a_pre @ wproj + bproj
    sgemm128<3><<<dim3(6, 128), 256>>>(f_, wproj, t_, bproj, BB * NN_, CCH, CCH);

    // MLP
    ln_row_kernel<<<BB * NN_, 256>>>(t_, ln2_g, ln2_b, f_, (const float*)0, CCH, 0);
    sgemm128<1><<<dim3(24, 128), 256>>>(f_, fc1_w, u_, fc1_b, BB * NN_, HIDD, CCH);
    ln_row_kernel<<<BB * NN_, 256>>>(u_, ml1_g, ml1_b, u_, (const float*)0, HIDD, 1);
    dwconv_kernel<<<dim3(HIDD / 128, NN_, BB), 128>>>(u_, dw_w, dw_b, u2_);
    sgemm128<1><<<dim3(6, 128), 256>>>(u2_, fc2_w, f_, fc2_b, BB * NN_, CCH, HIDD);
    ln_row_kernel<<<BB * NN_, 256>>>(f_, ml2_g, ml2_b, t_, t_, CCH, 2);  // t += LN(f)

    // t [B,N,C] -> out [B,C,N]
    transpose_kernel<<<dim3(24, 32, BB), dim3(32, 32)>>>(t_, outp, NN_, CCH);

    (void)in_sizes; (void)n_in; (void)out_size;
}